// round 6
// baseline (speedup 1.0000x reference)
#include <cuda_runtime.h>
#include <math.h>

#define TT 8192
#define KK 1024
#define DD 1024
#define NTH 1024
#define START_TAG 1022
#define STOP_TAG 1023
#define NEGV (-10000.0f)
#define LOG2E 1.4426950408889634f
#define LN2F 0.6931471805599453f

// ---------------- device scratch (no allocs allowed) ----------------
__device__ unsigned long long g_fvE[2][KK];       // (epoch<<32) | fv_bits, double-buffered
__device__ float g_gate[TT + 1];
__device__ float g_uc[TT], g_vc[TT], g_uu[TT], g_vu[TT];

__device__ __forceinline__ float ex2f(float x) {
    float y; asm("ex2.approx.f32 %0, %1;" : "=f"(y) : "f"(x)); return y;
}
__device__ __forceinline__ float lg2f(float x) {
    float y; asm("lg2.approx.f32 %0, %1;" : "=f"(y) : "f"(x)); return y;
}
// inf-proof helpers: clamp exp2 arg; floor log2 input
__device__ __forceinline__ float ex2s(float x) { return ex2f(fminf(x, 126.0f)); }
__device__ __forceinline__ float lg2s(float v) { return lg2f(fmaxf(v, 1e-37f)); }

__device__ __forceinline__ unsigned long long ldcg_u64(const unsigned long long* p) {
    unsigned long long v;
    asm volatile("ld.global.cg.u64 %0, [%1];" : "=l"(v) : "l"(p) : "memory");
    return v;
}
__device__ __forceinline__ void ldcg_v2(const unsigned long long* p,
                                        unsigned long long& a, unsigned long long& b) {
    asm volatile("ld.global.cg.v2.u64 {%0,%1}, [%2];" : "=l"(a), "=l"(b) : "l"(p) : "memory");
}
__device__ __forceinline__ void stcg_u64(unsigned long long* p, unsigned long long v) {
    asm volatile("st.global.cg.u64 [%0], %1;" :: "l"(p), "l"(v) : "memory");
}

// ---------------- prep 1: per-row dots with gate weight halves ----------------
__global__ void prep_dots(const float* __restrict__ reps,
                          const float* __restrict__ wc,
                          const float* __restrict__ wu) {
    int t = blockIdx.x, tid = threadIdx.x;                 // 256 threads
    const float4 a  = ((const float4*)(reps + (size_t)t * DD))[tid];
    const float4 c0 = ((const float4*)wc)[tid];
    const float4 c1 = ((const float4*)wc)[tid + 256];
    const float4 u0 = ((const float4*)wu)[tid];
    const float4 u1 = ((const float4*)wu)[tid + 256];
    float v0 = a.x * c0.x + a.y * c0.y + a.z * c0.z + a.w * c0.w;
    float v1 = a.x * c1.x + a.y * c1.y + a.z * c1.z + a.w * c1.w;
    float v2 = a.x * u0.x + a.y * u0.y + a.z * u0.z + a.w * u0.w;
    float v3 = a.x * u1.x + a.y * u1.y + a.z * u1.z + a.w * u1.w;
    #pragma unroll
    for (int o = 16; o; o >>= 1) {
        v0 += __shfl_xor_sync(0xffffffffu, v0, o);
        v1 += __shfl_xor_sync(0xffffffffu, v1, o);
        v2 += __shfl_xor_sync(0xffffffffu, v2, o);
        v3 += __shfl_xor_sync(0xffffffffu, v3, o);
    }
    __shared__ float sm[8][4];
    int lane = tid & 31, w = tid >> 5;
    if (lane == 0) { sm[w][0] = v0; sm[w][1] = v1; sm[w][2] = v2; sm[w][3] = v3; }
    __syncthreads();
    if (tid == 0) {
        float t0 = 0, t1 = 0, t2 = 0, t3 = 0;
        for (int i = 0; i < 8; i++) { t0 += sm[i][0]; t1 += sm[i][1]; t2 += sm[i][2]; t3 += sm[i][3]; }
        g_uc[t] = t0; g_vc[t] = t1; g_uu[t] = t2; g_vu[t] = t3;
    }
}

// ---------------- prep 2: gates + fvE init (fused) ----------------
__global__ void prep_gi(const int* __restrict__ spk) {
    int t = blockIdx.x * blockDim.x + threadIdx.x;
    if (t < TT) {
        int pt = (t > 0) ? t - 1 : 0;
        bool use_change = (t > 0) && (spk[t] != 0);
        float x = use_change ? (g_uc[pt] + g_vc[t]) : (g_uu[pt] + g_vu[t]);
        g_gate[t] = 1.0f / (1.0f + expf(-x));
    } else if (t == TT) {
        float x = g_uu[TT - 1] + g_vu[TT - 1];
        g_gate[TT] = 1.0f / (1.0f + expf(-x));
    }
    if (t < KK) {
        float v0 = (t == START_TAG) ? 0.0f : NEGV * LOG2E;
        g_fvE[0][t] = (unsigned long long)__float_as_uint(v0);       // epoch 0
        g_fvE[1][t] = 0xFFFFFFFF00000000ULL;                         // sentinel epoch
    }
}

// ---------------- persistent CRF forward (per-thread dataflow) ----------------
__global__ void __launch_bounds__(NTH, 1)
crf_main(const float* __restrict__ feats,
         const float* __restrict__ ti,
         const float* __restrict__ ta,
         float* __restrict__ out) {
    const int G   = gridDim.x;
    const int g   = blockIdx.x;
    const int tid = threadIdx.x;
    const int lane = tid & 31;
    const int wid  = tid >> 5;
    const int lrow = tid >> 7;            // 0..7 : row index within CTA
    const int j0   = (tid & 127) << 3;    // 8 prev-tags per thread (64B window)
    const int r0 = (g * KK) / G;
    const int r1 = ((g + 1) * KK) / G;
    const int R  = r1 - r0;               // rows per CTA (<= 8)
    const bool active = lrow < R;
    const int row = r0 + lrow;

    // pin matrix slice in registers, loaded straight from inputs
    float ta2r[8], df2r[8];
    if (active) {
        const float4* pa = (const float4*)(ta + (size_t)row * KK + j0);
        const float4* pi = (const float4*)(ti + (size_t)row * KK + j0);
        float4 a0 = pa[0], a1 = pa[1], i0 = pi[0], i1 = pi[1];
        ta2r[0]=a0.x*LOG2E; ta2r[1]=a0.y*LOG2E; ta2r[2]=a0.z*LOG2E; ta2r[3]=a0.w*LOG2E;
        ta2r[4]=a1.x*LOG2E; ta2r[5]=a1.y*LOG2E; ta2r[6]=a1.z*LOG2E; ta2r[7]=a1.w*LOG2E;
        df2r[0]=(i0.x-a0.x)*LOG2E; df2r[1]=(i0.y-a0.y)*LOG2E;
        df2r[2]=(i0.z-a0.z)*LOG2E; df2r[3]=(i0.w-a0.w)*LOG2E;
        df2r[4]=(i1.x-a1.x)*LOG2E; df2r[5]=(i1.y-a1.y)*LOG2E;
        df2r[6]=(i1.z-a1.z)*LOG2E; df2r[7]=(i1.w-a1.w)*LOG2E;
    } else {
        #pragma unroll
        for (int q = 0; q < 8; q++) { ta2r[q] = 0.0f; df2r[q] = 0.0f; }
    }

    __shared__ float s_gate[TT + 8];      // all gates resident in smem (32 KB)
    __shared__ float s_feat[4][8];        // feats ring, fed 2 steps ahead from registers
    __shared__ float s_part[8][4];
    __shared__ float s_red[32];
    __shared__ float s_ref;
    __shared__ float s_m;

    // prologue: gates to smem; prime feats ring; ref for t=0 is the known max (START=0)
    for (int i = tid; i <= TT; i += NTH) s_gate[i] = g_gate[i];
    float vf = 0.0f;
    if (wid == 16 && lane < R) {
        s_feat[0][lane] = feats[(size_t)0 * KK + r0 + lane] * LOG2E;
        s_feat[1][lane] = feats[(size_t)1 * KK + r0 + lane] * LOG2E;
        vf = feats[(size_t)2 * KK + r0 + lane];
    }
    if (tid == 0) s_ref = 0.0f;
    __syncthreads();

    for (int t = 0; t < TT; ++t) {
        const int p = t & 1;
        const unsigned ee = (unsigned)t;

        // feats ring: write slot t+2 (data already in register), issue LDG for t+3
        if (wid == 16 && lane < R) {
            if (t + 2 < TT) {
                s_feat[(t + 2) & 3][lane] = vf * LOG2E;
                if (t + 3 < TT) vf = feats[(size_t)(t + 3) * KK + r0 + lane];
            }
        }

        const float ref  = s_ref;         // written at finalize(t-1), ordered by BAR_B(t-1)
        const float gate = s_gate[t];

        // per-thread dataflow: poll ONLY this thread's 64B window; compute as soon
        // as it arrives (no grid-wide rendezvous before compute).
        float acc = 0.0f;
        if (active) {
            const unsigned long long* bp = &g_fvE[p][j0];
            unsigned long long a0, a1, a2, a3, a4, a5, a6, a7;
            for (;;) {
                ldcg_v2(bp,     a0, a1);
                ldcg_v2(bp + 2, a2, a3);
                ldcg_v2(bp + 4, a4, a5);
                ldcg_v2(bp + 6, a6, a7);
                unsigned long long d =
                    ((a0 >> 32) ^ ee) | ((a1 >> 32) ^ ee) |
                    ((a2 >> 32) ^ ee) | ((a3 >> 32) ^ ee) |
                    ((a4 >> 32) ^ ee) | ((a5 >> 32) ^ ee) |
                    ((a6 >> 32) ^ ee) | ((a7 >> 32) ^ ee);
                if (d == 0ull) break;
                __nanosleep(32);
            }
            float s0 = 0.0f, s1 = 0.0f;
            s0 += ex2s((__uint_as_float((unsigned)a0) - ref) + fmaf(gate, df2r[0], ta2r[0]));
            s1 += ex2s((__uint_as_float((unsigned)a1) - ref) + fmaf(gate, df2r[1], ta2r[1]));
            s0 += ex2s((__uint_as_float((unsigned)a2) - ref) + fmaf(gate, df2r[2], ta2r[2]));
            s1 += ex2s((__uint_as_float((unsigned)a3) - ref) + fmaf(gate, df2r[3], ta2r[3]));
            s0 += ex2s((__uint_as_float((unsigned)a4) - ref) + fmaf(gate, df2r[4], ta2r[4]));
            s1 += ex2s((__uint_as_float((unsigned)a5) - ref) + fmaf(gate, df2r[5], ta2r[5]));
            s0 += ex2s((__uint_as_float((unsigned)a6) - ref) + fmaf(gate, df2r[6], ta2r[6]));
            s1 += ex2s((__uint_as_float((unsigned)a7) - ref) + fmaf(gate, df2r[7], ta2r[7]));
            acc = s0 + s1;
        }
        #pragma unroll
        for (int o = 16; o; o >>= 1) acc += __shfl_xor_sync(0xffffffffu, acc, o);
        if (lane == 0) s_part[lrow][wid & 3] = acc;
        __syncthreads();                              // BAR_A

        // warp 0 finalizes all rows: combine partials, guarded log2, publish, next ref
        if (wid == 0) {
            int rr = lane >> 2;
            float v = s_part[rr][lane & 3];
            v += __shfl_xor_sync(0xffffffffu, v, 1);
            v += __shfl_xor_sync(0xffffffffu, v, 2);
            if ((lane & 3) == 0 && rr < R) {
                float fvnew = ref + s_feat[t & 3][rr] + lg2s(v);   // finite always
                unsigned long long packed =
                    ((unsigned long long)(unsigned)(t + 1) << 32) | __float_as_uint(fvnew);
                stcg_u64(&g_fvE[p ^ 1][r0 + rr], packed);
                if (rr == 0) s_ref = fvnew;           // current-row ref for next step
            }
        }
        __syncthreads();                              // BAR_B: s_ref visible to all
    }

    // ---------------- terminal: CTA owning STOP row ----------------
    if (g == G - 1) {
        const float gT = g_gate[TT];
        const bool mine = (lrow == R - 1);            // row == STOP_TAG
        float term[8];
        float lm = -3.0e38f;
        if (mine) {
            #pragma unroll
            for (int q = 0; q < 8; q++) {
                unsigned long long pk;
                do { pk = ldcg_u64(&g_fvE[0][j0 + q]); }         // TT even -> buffer 0
                while ((unsigned)(pk >> 32) != (unsigned)TT);
                float fvf = __uint_as_float((unsigned)pk);
                term[q] = fvf + fmaf(gT, df2r[q], ta2r[q]);
                lm = fmaxf(lm, term[q]);
            }
        }
        #pragma unroll
        for (int o = 16; o; o >>= 1) lm = fmaxf(lm, __shfl_xor_sync(0xffffffffu, lm, o));
        if (lane == 0) s_red[wid] = lm;
        __syncthreads();
        if (wid == 0) {
            float m = s_red[lane];
            #pragma unroll
            for (int o = 16; o; o >>= 1) m = fmaxf(m, __shfl_xor_sync(0xffffffffu, m, o));
            if (lane == 0) s_m = m;
        }
        __syncthreads();
        const float M = s_m;
        float s = 0.0f;
        if (mine) {
            #pragma unroll
            for (int q = 0; q < 8; q++) s += ex2s(term[q] - M);
        }
        #pragma unroll
        for (int o = 16; o; o >>= 1) s += __shfl_xor_sync(0xffffffffu, s, o);
        if (lane == 0) s_red[wid] = s;
        __syncthreads();
        if (tid == 0) {
            float tot = 0.0f;
            for (int w = 0; w < 32; w++) tot += s_red[w];
            out[0] = (M + lg2s(tot)) * LN2F;          // back to natural log
        }
    }
}

// ---------------- launch ----------------
extern "C" void kernel_launch(void* const* d_in, const int* in_sizes, int n_in,
                              void* d_out, int out_size) {
    const float* feats = (const float*)d_in[0];
    const float* reps  = (const float*)d_in[1];
    const float* wc    = (const float*)d_in[2];
    const float* wu    = (const float*)d_in[3];
    const float* ti    = (const float*)d_in[4];
    const float* ta    = (const float*)d_in[5];
    const int*   spk   = (const int*)d_in[6];

    int dev = 0; cudaGetDevice(&dev);
    int sm = 148;
    cudaDeviceGetAttribute(&sm, cudaDevAttrMultiProcessorCount, dev);
    int grid = sm;
    if (grid > 256) grid = 256;
    if (grid < 128) grid = 128;    // row mapping needs <=8 rows/CTA

    prep_dots<<<TT, 256>>>(reps, wc, wu);
    prep_gi<<<(TT + 1 + 1023) / 1024, 1024>>>(spk);
    crf_main<<<grid, NTH>>>(feats, ti, ta, (float*)d_out);
}

// round 7
// speedup vs baseline: 3.1806x; 3.1806x over previous
#include <cuda_runtime.h>
#include <math.h>

#define TT 8192
#define KK 1024
#define DD 1024
#define NTH 1024
#define NR 8                      // fv replicas (spread L2 slice pressure)
#define START_TAG 1022
#define STOP_TAG 1023
#define NEGV (-10000.0f)
#define LOG2E 1.4426950408889634f
#define LN2F 0.6931471805599453f

// ---------------- device scratch (no allocs; persistent across calls) ----------------
__device__ __align__(128) unsigned long long g_fvE[2][NR][KK]; // (epoch<<32)|fv_bits
__device__ float g_uc[TT], g_vc[TT], g_uu[TT], g_vu[TT];
__device__ float g_gate[TT + 1];
__device__ unsigned g_sync;       // monotonic counter barrier (never reset)

__device__ __forceinline__ float ex2f(float x) {
    float y; asm("ex2.approx.f32 %0, %1;" : "=f"(y) : "f"(x)); return y;
}
__device__ __forceinline__ float lg2f(float x) {
    float y; asm("lg2.approx.f32 %0, %1;" : "=f"(y) : "f"(x)); return y;
}
__device__ __forceinline__ float ex2s(float x) { return ex2f(fminf(x, 126.0f)); }
__device__ __forceinline__ float lg2s(float v) { return lg2f(fmaxf(v, 1e-37f)); }

__device__ __forceinline__ unsigned long long ldcg_u64(const unsigned long long* p) {
    unsigned long long v;
    asm volatile("ld.global.cg.u64 %0, [%1];" : "=l"(v) : "l"(p) : "memory");
    return v;
}
__device__ __forceinline__ void ldcg_v2(const unsigned long long* p,
                                        unsigned long long& a, unsigned long long& b) {
    asm volatile("ld.global.cg.v2.u64 {%0,%1}, [%2];" : "=l"(a), "=l"(b) : "l"(p) : "memory");
}
__device__ __forceinline__ void stcg_u64(unsigned long long* p, unsigned long long v) {
    asm volatile("st.global.cg.u64 [%0], %1;" :: "l"(p), "l"(v) : "memory");
}
__device__ __forceinline__ unsigned ld_acq(const unsigned* p) {
    unsigned v;
    asm volatile("ld.acquire.gpu.u32 %0, [%1];" : "=r"(v) : "l"(p) : "memory");
    return v;
}

// one-time grid barrier: monotonic counter, works across harness replays w/o reset
__device__ __forceinline__ void gsync(int G, int tid) {
    __syncthreads();
    if (tid == 0) {
        __threadfence();
        unsigned my = atomicAdd(&g_sync, 1u);
        unsigned goal = my - (my % (unsigned)G) + (unsigned)G;
        while (ld_acq(&g_sync) < goal) { __nanosleep(64); }
    }
    __syncthreads();
}

// ---------------- single persistent kernel: prep + CRF forward ----------------
__global__ void __launch_bounds__(NTH, 1)
crf_main(const float* __restrict__ feats,
         const float* __restrict__ reps,
         const float* __restrict__ wc,
         const float* __restrict__ wu,
         const float* __restrict__ ti,
         const float* __restrict__ ta,
         const int*   __restrict__ spk,
         float* __restrict__ out) {
    const int G   = gridDim.x;
    const int g   = blockIdx.x;
    const int tid = threadIdx.x;
    const int lane = tid & 31;
    const int wid  = tid >> 5;
    const int lrow = tid >> 7;            // 0..7 : row index within CTA
    const int j0   = (tid & 127) << 3;    // 8 prev-tags per thread
    const int r0 = (g * KK) / G;
    const int r1 = ((g + 1) * KK) / G;
    const int R  = r1 - r0;               // rows per CTA (<= 8)
    const bool active = lrow < R;
    const int row = r0 + lrow;
    const int rep = g & (NR - 1);

    // ---- phase 0: warp-distributed gate dot products + fvE init ----
    {
        const int wgid = g * 32 + wid;
        #pragma unroll
        for (int m = 0; m < 2; m++) {
            int t = wgid + G * 32 * m;
            if (t < TT) {
                const float4* rp = (const float4*)(reps + (size_t)t * DD);
                float d0 = 0, d1 = 0, d2 = 0, d3 = 0;
                for (int i = lane; i < 256; i += 32) {
                    float4 r  = rp[i];
                    float4 c0 = ((const float4*)wc)[i];
                    float4 c1 = ((const float4*)wc)[i + 256];
                    float4 u0 = ((const float4*)wu)[i];
                    float4 u1 = ((const float4*)wu)[i + 256];
                    d0 += r.x*c0.x + r.y*c0.y + r.z*c0.z + r.w*c0.w;
                    d1 += r.x*c1.x + r.y*c1.y + r.z*c1.z + r.w*c1.w;
                    d2 += r.x*u0.x + r.y*u0.y + r.z*u0.z + r.w*u0.w;
                    d3 += r.x*u1.x + r.y*u1.y + r.z*u1.z + r.w*u1.w;
                }
                #pragma unroll
                for (int o = 16; o; o >>= 1) {
                    d0 += __shfl_xor_sync(0xffffffffu, d0, o);
                    d1 += __shfl_xor_sync(0xffffffffu, d1, o);
                    d2 += __shfl_xor_sync(0xffffffffu, d2, o);
                    d3 += __shfl_xor_sync(0xffffffffu, d3, o);
                }
                if (lane == 0) { g_uc[t] = d0; g_vc[t] = d1; g_uu[t] = d2; g_vu[t] = d3; }
            }
        }
        if (g == 0) {
            float v0 = (tid == START_TAG) ? 0.0f : NEGV * LOG2E;
            #pragma unroll
            for (int r = 0; r < NR; r++) {
                g_fvE[0][r][tid] = (unsigned long long)__float_as_uint(v0);   // epoch 0
                g_fvE[1][r][tid] = 0xFFFFFFFF00000000ULL;                     // sentinel
            }
        }
    }
    gsync(G, tid);

    // ---- phase 1: gates (distributed) ----
    {
        int idx = g * NTH + tid;          // G*NTH > TT+1 -> single pass
        if (idx < TT) {
            int pt = idx ? idx - 1 : 0;
            bool uc_ = (idx > 0) && (spk[idx] != 0);
            float x = uc_ ? (g_uc[pt] + g_vc[idx]) : (g_uu[pt] + g_vu[idx]);
            g_gate[idx] = 1.0f / (1.0f + expf(-x));
        } else if (idx == TT) {
            float x = g_uu[TT - 1] + g_vu[TT - 1];
            g_gate[TT] = 1.0f / (1.0f + expf(-x));
        }
    }
    gsync(G, tid);

    // ---- pin matrix slice in registers ----
    float ta2r[8], df2r[8];
    if (active) {
        const float4* pa = (const float4*)(ta + (size_t)row * KK + j0);
        const float4* pi = (const float4*)(ti + (size_t)row * KK + j0);
        float4 a0 = pa[0], a1 = pa[1], i0 = pi[0], i1 = pi[1];
        ta2r[0]=a0.x*LOG2E; ta2r[1]=a0.y*LOG2E; ta2r[2]=a0.z*LOG2E; ta2r[3]=a0.w*LOG2E;
        ta2r[4]=a1.x*LOG2E; ta2r[5]=a1.y*LOG2E; ta2r[6]=a1.z*LOG2E; ta2r[7]=a1.w*LOG2E;
        df2r[0]=(i0.x-a0.x)*LOG2E; df2r[1]=(i0.y-a0.y)*LOG2E;
        df2r[2]=(i0.z-a0.z)*LOG2E; df2r[3]=(i0.w-a0.w)*LOG2E;
        df2r[4]=(i1.x-a1.x)*LOG2E; df2r[5]=(i1.y-a1.y)*LOG2E;
        df2r[6]=(i1.z-a1.z)*LOG2E; df2r[7]=(i1.w-a1.w)*LOG2E;
    } else {
        #pragma unroll
        for (int q = 0; q < 8; q++) { ta2r[q] = 0.0f; df2r[q] = 0.0f; }
    }

    __shared__ float s_gate[TT + 8];
    __shared__ __align__(16) float s_fvp[KK];
    __shared__ float s_feat[4][8];
    __shared__ float s_part[8][4];
    __shared__ float s_red[32];
    __shared__ float s_ref;
    __shared__ float s_m;

    for (int i = tid; i <= TT; i += NTH) s_gate[i] = g_gate[i];
    float vf = 0.0f;
    if (wid == 31 && lane < R) {
        s_feat[0][lane] = feats[r0 + lane] * LOG2E;
        s_feat[1][lane] = feats[(size_t)KK + r0 + lane] * LOG2E;
        vf = feats[(size_t)2 * KK + r0 + lane];
    }
    if (tid == 0) s_ref = 0.0f;
    __syncthreads();

    // ---- main sequential loop ----
    for (int t = 0; t < TT; ++t) {
        const int p = t & 1;
        const unsigned ee = (unsigned)t;

        // feats ring: write slot t+2 (value already in register), issue LDG for t+3
        if (wid == 31 && lane < R && (t + 2) < TT) {
            s_feat[(t + 2) & 3][lane] = vf * LOG2E;
            if (t + 3 < TT) vf = feats[(size_t)(t + 3) * KK + r0 + lane];
        }

        // stage: 512 threads, 16B vector polls on this CTA's replica
        // (8 req/line/CTA; ~18 CTAs/replica -> ~150 req/line/round vs 2400 before)
        if (tid < 512) {
            const unsigned long long* bp = &g_fvE[p][rep][2 * tid];
            unsigned long long a0, a1;
            for (;;) {
                ldcg_v2(bp, a0, a1);
                if (((((a0 >> 32) ^ ee) | ((a1 >> 32) ^ ee))) == 0ull) break;
                __nanosleep(32);
            }
            s_fvp[2 * tid]     = __uint_as_float((unsigned)a0);
            s_fvp[2 * tid + 1] = __uint_as_float((unsigned)a1);
        }
        __syncthreads();                              // BAR_S

        const float ref  = s_ref;                     // written at finalize(t-1), safe
        const float gate = s_gate[t];

        float acc = 0.0f;
        if (active) {
            float4 f0 = *(const float4*)&s_fvp[j0];
            float4 f1 = *(const float4*)&s_fvp[j0 + 4];
            float s0 = 0.0f, s1 = 0.0f;
            s0 += ex2s((f0.x - ref) + fmaf(gate, df2r[0], ta2r[0]));
            s1 += ex2s((f0.y - ref) + fmaf(gate, df2r[1], ta2r[1]));
            s0 += ex2s((f0.z - ref) + fmaf(gate, df2r[2], ta2r[2]));
            s1 += ex2s((f0.w - ref) + fmaf(gate, df2r[3], ta2r[3]));
            s0 += ex2s((f1.x - ref) + fmaf(gate, df2r[4], ta2r[4]));
            s1 += ex2s((f1.y - ref) + fmaf(gate, df2r[5], ta2r[5]));
            s0 += ex2s((f1.z - ref) + fmaf(gate, df2r[6], ta2r[6]));
            s1 += ex2s((f1.w - ref) + fmaf(gate, df2r[7], ta2r[7]));
            acc = s0 + s1;
        }
        #pragma unroll
        for (int o = 16; o; o >>= 1) acc += __shfl_xor_sync(0xffffffffu, acc, o);
        if (lane == 0) s_part[lrow][wid & 3] = acc;
        __syncthreads();                              // BAR_A

        // warp 0: combine, lg2, publish to ALL replicas, set next ref
        if (wid == 0) {
            int rr = lane >> 2;
            float v = s_part[rr][lane & 3];
            v += __shfl_xor_sync(0xffffffffu, v, 1);
            v += __shfl_xor_sync(0xffffffffu, v, 2);
            if ((lane & 3) == 0 && rr < R) {
                float fvnew = ref + s_feat[t & 3][rr] + lg2s(v);
                unsigned long long packed =
                    ((unsigned long long)(unsigned)(t + 1) << 32) | __float_as_uint(fvnew);
                #pragma unroll
                for (int r = 0; r < NR; r++)
                    stcg_u64(&g_fvE[p ^ 1][r][r0 + rr], packed);
                if (rr == 0) s_ref = fvnew;
            }
        }
        // no trailing bar: partial/stage writes of t+1 are ordered behind BAR_S(t+1),
        // which warp 0 joins only after finalize; s_ref read after BAR_S(t+1).
    }

    // ---------------- terminal: CTA owning STOP row ----------------
    if (g == G - 1) {
        const float gT = s_gate[TT];
        const bool mine = (lrow == R - 1);            // row == STOP_TAG
        float term[8];
        float lm = -3.0e38f;
        if (mine) {
            #pragma unroll
            for (int q = 0; q < 8; q++) {
                unsigned long long pk;
                do { pk = ldcg_u64(&g_fvE[0][rep][j0 + q]); }    // TT even -> buffer 0
                while ((unsigned)(pk >> 32) != (unsigned)TT);
                float fvf = __uint_as_float((unsigned)pk);
                term[q] = fvf + fmaf(gT, df2r[q], ta2r[q]);
                lm = fmaxf(lm, term[q]);
            }
        }
        #pragma unroll
        for (int o = 16; o; o >>= 1) lm = fmaxf(lm, __shfl_xor_sync(0xffffffffu, lm, o));
        if (lane == 0) s_red[wid] = lm;
        __syncthreads();
        if (wid == 0) {
            float m = s_red[lane];
            #pragma unroll
            for (int o = 16; o; o >>= 1) m = fmaxf(m, __shfl_xor_sync(0xffffffffu, m, o));
            if (lane == 0) s_m = m;
        }
        __syncthreads();
        const float M = s_m;
        float s = 0.0f;
        if (mine) {
            #pragma unroll
            for (int q = 0; q < 8; q++) s += ex2s(term[q] - M);
        }
        #pragma unroll
        for (int o = 16; o; o >>= 1) s += __shfl_xor_sync(0xffffffffu, s, o);
        if (lane == 0) s_red[wid] = s;
        __syncthreads();
        if (tid == 0) {
            float tot = 0.0f;
            for (int w = 0; w < 32; w++) tot += s_red[w];
            out[0] = (M + lg2s(tot)) * LN2F;          // back to natural log
        }
    }
}

// ---------------- launch: ONE kernel (ncu -s 5 -c 1 must capture crf_main) ----------------
extern "C" void kernel_launch(void* const* d_in, const int* in_sizes, int n_in,
                              void* d_out, int out_size) {
    const float* feats = (const float*)d_in[0];
    const float* reps  = (const float*)d_in[1];
    const float* wc    = (const float*)d_in[2];
    const float* wu    = (const float*)d_in[3];
    const float* ti    = (const float*)d_in[4];
    const float* ta    = (const float*)d_in[5];
    const int*   spk   = (const int*)d_in[6];

    int dev = 0; cudaGetDevice(&dev);
    int sm = 148;
    cudaDeviceGetAttribute(&sm, cudaDevAttrMultiProcessorCount, dev);
    int grid = sm;
    if (grid > 256) grid = 256;
    if (grid < 128) grid = 128;    // needs <=8 rows/CTA and dot coverage G*64>=TT

    crf_main<<<grid, NTH>>>(feats, reps, wc, wu, ti, ta, spk, (float*)d_out);
}